// round 10
// baseline (speedup 1.0000x reference)
#include <cuda_runtime.h>

typedef unsigned long long u64;

// x [16,3,256,256] f32, thetas[12], phis[3] -> out [16,1,128,128] f32
#define PPAIRS (16 * 128 * 64)   // 131072 threads, 2 patches each

// ---- packed f32x2 helpers (lanes = 2 adjacent patches) ----
__device__ __forceinline__ u64 pk2(float lo, float hi) {
    u64 r; asm("mov.b64 %0,{%1,%2};" : "=l"(r) : "f"(lo), "f"(hi)); return r;
}
__device__ __forceinline__ u64 pk2b(float v) { return pk2(v, v); }
__device__ __forceinline__ void upk2(float& lo, float& hi, u64 v) {
    asm("mov.b64 {%0,%1},%2;" : "=f"(lo), "=f"(hi) : "l"(v));
}
__device__ __forceinline__ u64 fma2(u64 a, u64 b, u64 c) {
    u64 d; asm("fma.rn.f32x2 %0,%1,%2,%3;" : "=l"(d) : "l"(a), "l"(b), "l"(c)); return d;
}
__device__ __forceinline__ u64 mul2(u64 a, u64 b) {
    u64 d; asm("mul.rn.f32x2 %0,%1,%2;" : "=l"(d) : "l"(a), "l"(b)); return d;
}
__device__ __forceinline__ u64 neg2(u64 a) {
    const u64 SGN = 0x8000000080000000ULL;
    u64 d; asm("xor.b64 %0,%1,%2;" : "=l"(d) : "l"(a), "l"(SGN)); return d;
}

struct CS { u64 c, s; };
__device__ __forceinline__ CS cs2(float alo, float ahi) {
    float sl, cl, sh, ch;
    __sincosf(0.5f * alo, &sl, &cl);
    __sincosf(0.5f * ahi, &sh, &ch);
    CS r; r.c = pk2(cl, ch); r.s = pk2(sl, sh); return r;
}
struct CT { u64 c, t; };  // cos (uniform scale) + tan (butterfly)
__device__ __forceinline__ CT ct2(float alo, float ahi) {
    float sl, cl, sh, ch;
    __sincosf(0.5f * alo, &sl, &cl);
    __sincosf(0.5f * ahi, &sh, &ch);
    CT r; r.c = pk2(cl, ch);
    r.t = pk2(__fdividef(sl, cl), __fdividef(sh, ch));
    return r;
}

// CU-ring monomial: new[PERM[k]] = coef[k] * old[k] (per 4-wire half-space).
// k=0 is a fixed point with coef 1. 15-cycle in application order:
__device__ __constant__ const int CYC[15] = {1,9,14,3,2,11,5,6,4,15,10,12,8,7,13};

// In-place monomial over 16 amps at offset O, coefs from SMEM (u64 packed-dup).
__device__ __forceinline__ void mono_smem(u64* sr, u64* si, int O,
                                          const u64* __restrict__ cr,
                                          const u64* __restrict__ ci) {
    u64 tR = sr[O + 13], tI = si[O + 13];
#pragma unroll
    for (int ii = 13; ii >= 0; ii--) {
        const int s_ = CYC[ii], d_ = CYC[ii + 1];
        u64 crk = cr[s_], cik = ci[s_];
        u64 ar = sr[O + s_], ai = si[O + s_];
        sr[O + d_] = fma2(neg2(cik), ai, mul2(crk, ar));
        si[O + d_] = fma2(cik, ar, mul2(crk, ai));
    }
    {   // close the cycle: new[CYC[0]=1] = c[13] * old[13]
        u64 crk = cr[13], cik = ci[13];
        sr[O + 1] = fma2(neg2(cik), tI, mul2(crk, tR));
        si[O + 1] = fma2(cik, tR, mul2(crk, tI));
    }
}

// Full 32-amp state: k = w0*16 + n,  n = w1*8 + w2*4 + w3*2 + w4
__global__ void __launch_bounds__(128, 3)
sim_kernel(const float* __restrict__ x,
           const float* __restrict__ thetas,
           const float* __restrict__ phis,
           float* __restrict__ out) {
    // Per-block gate-constant tables: lower (w0=0) and upper (w0=1, CPhase-folded).
    __shared__ u64 cLr[3][16], cLi[3][16];
    __shared__ u64 cUr[3][16], cUi[3][16];

    int tid = threadIdx.x;
    if (tid < 48) {
        int L = tid >> 4, k = tid & 15;
        const int cb[4] = {8, 4, 2, 1};
        const int tb[4] = {4, 2, 1, 8};
        float cr = 1.f, ci = 0.f;
        int m = k;
#pragma unroll
        for (int w = 0; w < 4; w++) {
            if (m & cb[w]) {
                float s_, c_;
                __sincosf(0.5f * thetas[4 * L + w], &s_, &c_);
                float fr, fi;
                if (m & tb[w]) { fr = s_;  fi = -c_; }   // f1 = sin - i cos
                else           { fr = -s_; fi = -c_; }   // f2 = -sin - i cos
                float nr = cr * fr - ci * fi;
                float ni = cr * fi + ci * fr;
                cr = nr; ci = ni;
                m ^= tb[w];
            }
        }
        cLr[L][k] = pk2b(cr); cLi[L][k] = pk2b(ci);
        float ur = cr, ui = ci;                  // upper: fold CPhase(phi_L) on dest&8
        if (m & 8) {
            float ps, pc;
            __sincosf(phis[L], &ps, &pc);
            ur = cr * pc - ci * ps;
            ui = cr * ps + ci * pc;
        }
        cUr[L][k] = pk2b(ur); cUi[L][k] = pk2b(ui);
    }
    __syncthreads();

    int q   = blockIdx.x * 128 + tid;
    int b   = q >> 13;
    int rem = q & 8191;
    int i   = rem >> 6;
    int jp  = rem & 63;

    const float4* __restrict__ x4 = (const float4*)x;

    u64 sr[32], si[32];

    // ================= Layer 0: product state (16 amps) =================
    {
        int base = ((b * 3 + 0) * 256 + 2 * i) * 64 + jp;
        float4 v0 = x4[base];
        float4 v1 = x4[base + 64];
        CS g0 = cs2(v0.x, v0.z), g1 = cs2(v0.y, v0.w);
        CS g2 = cs2(v1.x, v1.z), g3 = cs2(v1.y, v1.w);

        u64 INV2 = pk2b(0.70710678118654752f);
        u64 c0 = mul2(g0.c, INV2), s0 = mul2(g0.s, INV2);
        u64 ab[4] = { mul2(c0, g1.c), mul2(c0, g1.s), mul2(s0, g1.c), mul2(s0, g1.s) };
        u64 cd[4] = { mul2(g2.c, g3.c), mul2(g2.c, g3.s), mul2(g2.s, g3.c), mul2(g2.s, g3.s) };
#pragma unroll
        for (int n = 0; n < 16; n++) {
            u64 m = mul2(ab[n >> 2], cd[n & 3]);
            int pc = __popc(n) & 3;
            if (pc == 0)      { sr[n] = m;        si[n] = 0ULL;     }
            else if (pc == 1) { sr[n] = 0ULL;     si[n] = neg2(m);  }
            else if (pc == 2) { sr[n] = neg2(m);  si[n] = 0ULL;     }
            else              { sr[n] = 0ULL;     si[n] = m;        }
        }
    }

    // ---- Layer-0 CU ring as monomial on the 16-amp state (wire0 untouched) --
    mono_smem(sr, si, 0, cLr[0], cLi[0]);

    // ---- Split into wire0 branches at CPhase-0 ----
    {
        float ps_, pc_;
        __sincosf(phis[0], &ps_, &pc_);
        u64 pr = pk2b(pc_), pi = pk2b(ps_);
        u64 npi = neg2(pi);
#pragma unroll
        for (int n = 0; n < 16; n++) {
            if (n & 8) {
                sr[16 + n] = fma2(npi, si[n], mul2(pr, sr[n]));
                si[16 + n] = fma2(pi,  sr[n], mul2(pr, si[n]));
            } else {
                sr[16 + n] = sr[n];
                si[16 + n] = si[n];
            }
        }
    }

    u64 Cacc = pk2b(1.0f);  // packed uniform RX cos scale (layers 1,2)

    // ================= Layers 1, 2 =================
#pragma unroll
    for (int L = 1; L < 3; L++) {
        int base = ((b * 3 + L) * 256 + 2 * i) * 64 + jp;
        float4 v0 = x4[base];
        float4 v1 = x4[base + 64];
        CT g[4] = { ct2(v0.x, v0.z), ct2(v0.y, v0.w),
                    ct2(v1.x, v1.z), ct2(v1.y, v1.w) };

        // RX via tan trick: RX/c = [[1,-it],[-it,1]]  (dense, 32 amps)
#pragma unroll
        for (int w = 0; w < 4; w++) {
            Cacc = mul2(Cacc, g[w].c);
            u64 t = g[w].t, nt = neg2(t);
            int m = 8 >> w;
#pragma unroll
            for (int k = 0; k < 32; k++) {
                if (!(k & m)) {
                    int k1 = k | m;
                    u64 a0r = sr[k],  a0i = si[k];
                    u64 a1r = sr[k1], a1i = si[k1];
                    sr[k]  = fma2(t,  a1i, a0r);
                    si[k]  = fma2(nt, a1r, a0i);
                    sr[k1] = fma2(t,  a0i, a1r);
                    si[k1] = fma2(nt, a0r, a1i);
                }
            }
        }

        // CU ring (+ folded CPhase on the upper half) as monomials
        mono_smem(sr, si, 0,  cLr[L], cLi[L]);
        mono_smem(sr, si, 16, cUr[L], cUi[L]);
    }

    // Final H on wire0 + <Z0>: ev = 2*C^2 * sum_n Re(conj(a_n) b_n)
    // (all CPhase phases already in the state/coefs)
    u64 acc = 0ULL;
#pragma unroll
    for (int n = 0; n < 16; n++) {
        acc = fma2(sr[n], sr[n + 16], acc);
        acc = fma2(si[n], si[n + 16], acc);
    }
    u64 C2 = mul2(Cacc, Cacc);
    acc = mul2(acc, mul2(C2, pk2b(2.0f)));

    float lo, hi;
    upk2(lo, hi, acc);
    ((float2*)out)[q] = make_float2(lo, hi);
}

extern "C" void kernel_launch(void* const* d_in, const int* in_sizes, int n_in,
                              void* d_out, int out_size) {
    const float* x      = (const float*)d_in[0];
    const float* thetas = (const float*)d_in[1];
    const float* phis   = (const float*)d_in[2];
    float* out = (float*)d_out;

    sim_kernel<<<PPAIRS / 128, 128>>>(x, thetas, phis, out);
}

// round 11
// speedup vs baseline: 1.0171x; 1.0171x over previous
#include <cuda_runtime.h>

typedef unsigned long long u64;

// x [16,3,256,256] f32, thetas[12], phis[3] -> out [16,1,128,128] f32
#define PPAIRS (16 * 128 * 64)   // 131072 threads, 2 patches each

// ---- packed f32x2 helpers (lanes = 2 adjacent patches) ----
__device__ __forceinline__ u64 pk2(float lo, float hi) {
    u64 r; asm("mov.b64 %0,{%1,%2};" : "=l"(r) : "f"(lo), "f"(hi)); return r;
}
__device__ __forceinline__ u64 pk2b(float v) { return pk2(v, v); }
__device__ __forceinline__ void upk2(float& lo, float& hi, u64 v) {
    asm("mov.b64 {%0,%1},%2;" : "=f"(lo), "=f"(hi) : "l"(v));
}
__device__ __forceinline__ u64 fma2(u64 a, u64 b, u64 c) {
    u64 d; asm("fma.rn.f32x2 %0,%1,%2,%3;" : "=l"(d) : "l"(a), "l"(b), "l"(c)); return d;
}
__device__ __forceinline__ u64 mul2(u64 a, u64 b) {
    u64 d; asm("mul.rn.f32x2 %0,%1,%2;" : "=l"(d) : "l"(a), "l"(b)); return d;
}
__device__ __forceinline__ u64 neg2(u64 a) {
    const u64 SGN = 0x8000000080000000ULL;
    u64 d; asm("xor.b64 %0,%1,%2;" : "=l"(d) : "l"(a), "l"(SGN)); return d;
}

struct CS { u64 c, s; };
__device__ __forceinline__ CS cs2(float alo, float ahi) {
    float sl, cl, sh, ch;
    __sincosf(0.5f * alo, &sl, &cl);
    __sincosf(0.5f * ahi, &sh, &ch);
    CS r; r.c = pk2(cl, ch); r.s = pk2(sl, sh); return r;
}
struct CT { u64 c, t; };  // cos (uniform scale) + tan (butterfly)
__device__ __forceinline__ CT ct2(float alo, float ahi) {
    float sl, cl, sh, ch;
    __sincosf(0.5f * alo, &sl, &cl);
    __sincosf(0.5f * ahi, &sh, &ch);
    CT r; r.c = pk2(cl, ch);
    r.t = pk2(__fdividef(sl, cl), __fdividef(sh, ch));
    return r;
}

// packed complex
struct Cp { u64 r, i; };
__device__ __forceinline__ Cp cmul(Cp a, Cp b) {
    Cp d;
    d.r = fma2(neg2(a.i), b.i, mul2(a.r, b.r));
    d.i = fma2(a.i, b.r, mul2(a.r, b.i));
    return d;
}

// CU-ring monomial: new[PERM[k]] = coef[k] * old[k] (per 4-wire half-space).
// f1 = sin - i cos (ctrl&tgt both 1), f2 = -conj(f1). k=0 fixed point, coef 1.
__device__ __forceinline__ void coef_table(const float* __restrict__ thetas,
                                           int L, Cp* c) {
    Cp f1[4], f2[4];
#pragma unroll
    for (int w = 0; w < 4; w++) {
        float s_, c_;
        __sincosf(0.5f * thetas[4 * L + w], &s_, &c_);
        f1[w].r = pk2b(s_);  f1[w].i = pk2b(-c_);
        f2[w].r = neg2(f1[w].r);  f2[w].i = f1[w].i;   // f2 = -conj(f1)
    }
    c[1]  = f2[3];
    c[3]  = f1[2];
    c[6]  = f1[1];
    c[12] = f1[0];
    c[2]  = cmul(f2[2], f2[3]);
    c[4]  = cmul(f2[1], c[2]);
    c[5]  = cmul(f2[1], f1[2]);
    c[7]  = cmul(f1[1], f2[3]);
    Cp E  = cmul(f2[0], f2[1]);
    c[9]  = cmul(E, f1[2]);
    Cp T  = cmul(f2[2], f1[3]);
    c[8]  = cmul(E, T);
    c[10] = cmul(f2[0], f1[1]);
    c[11] = cmul(c[10], f1[3]);
    c[13] = cmul(f1[0], f1[3]);
    c[14] = cmul(c[13], f2[2]);
    c[15] = cmul(f1[0], f1[2]);
}

__device__ __constant__ const int PERM[16] = {0,9,11,2,15,6,4,13,7,14,12,5,8,1,3,10};

// Apply monomial in place over 16 amps at offset O.
__device__ __forceinline__ void mono_apply(u64* sr, u64* si, int O, const Cp* c) {
    u64 tr[16], ti[16];
    tr[0] = sr[O]; ti[0] = si[O];
#pragma unroll
    for (int k = 1; k < 16; k++) {
        int m = PERM[k];
        u64 ar = sr[O + k], ai = si[O + k];
        u64 nci = neg2(c[k].i);
        tr[m] = fma2(nci,    ai, mul2(c[k].r, ar));
        ti[m] = fma2(c[k].i, ar, mul2(c[k].r, ai));
    }
#pragma unroll
    for (int k = 0; k < 16; k++) { sr[O + k] = tr[k]; si[O + k] = ti[k]; }
}

// Full 32-amp state: k = w0*16 + n,  n = w1*8 + w2*4 + w3*2 + w4
__global__ void __launch_bounds__(128, 3)
sim_kernel(const float* __restrict__ x,
           const float* __restrict__ thetas,
           const float* __restrict__ phis,
           float* __restrict__ out) {
    int q   = blockIdx.x * 128 + threadIdx.x;
    int b   = q >> 13;
    int rem = q & 8191;
    int i   = rem >> 6;
    int jp  = rem & 63;

    const float4* __restrict__ x4 = (const float4*)x;
    int base0 = ((b * 3 + 0) * 256 + 2 * i) * 64 + jp;
    int base1 = base0 + 256 * 64;    // channel L+1 offset: 256 rows * 64 float4
    int base2 = base1 + 256 * 64;

    // ---- software-pipelined loads: L0 + L1 in flight immediately ----
    float4 va0 = x4[base0], va1 = x4[base0 + 64];
    float4 vb0 = x4[base1], vb1 = x4[base1 + 64];

    u64 sr[32], si[32];

    // ================= Layer 0: product state (16 amps) =================
    {
        CS g0 = cs2(va0.x, va0.z), g1 = cs2(va0.y, va0.w);
        CS g2 = cs2(va1.x, va1.z), g3 = cs2(va1.y, va1.w);

        u64 INV2 = pk2b(0.70710678118654752f);
        u64 c0 = mul2(g0.c, INV2), s0 = mul2(g0.s, INV2);
        u64 ab[4] = { mul2(c0, g1.c), mul2(c0, g1.s), mul2(s0, g1.c), mul2(s0, g1.s) };
        u64 cd[4] = { mul2(g2.c, g3.c), mul2(g2.c, g3.s), mul2(g2.s, g3.c), mul2(g2.s, g3.s) };
#pragma unroll
        for (int n = 0; n < 16; n++) {
            u64 m = mul2(ab[n >> 2], cd[n & 3]);
            int pc = __popc(n) & 3;
            if (pc == 0)      { sr[n] = m;        si[n] = 0ULL;     }
            else if (pc == 1) { sr[n] = 0ULL;     si[n] = neg2(m);  }
            else if (pc == 2) { sr[n] = neg2(m);  si[n] = 0ULL;     }
            else              { sr[n] = 0ULL;     si[n] = m;        }
        }
    }

    // ---- Layer-0 CU ring as monomial on the 16-amp state ----
    {
        Cp c[16];
        coef_table(thetas, 0, c);
        mono_apply(sr, si, 0, c);
    }

    // ---- Split into wire0 branches at CPhase-0 ----
    {
        float ps_, pc_;
        __sincosf(phis[0], &ps_, &pc_);
        u64 pr = pk2b(pc_), pi = pk2b(ps_);
        u64 npi = neg2(pi);
#pragma unroll
        for (int n = 0; n < 16; n++) {
            if (n & 8) {
                sr[16 + n] = fma2(npi, si[n], mul2(pr, sr[n]));
                si[16 + n] = fma2(pi,  sr[n], mul2(pr, si[n]));
            } else {
                sr[16 + n] = sr[n];
                si[16 + n] = si[n];
            }
        }
    }

    u64 Cacc = pk2b(1.0f);  // packed uniform RX cos scale (layers 1,2)

    // ---- prefetch layer-2 pixels before layer-1 compute ----
    float4 vc0 = x4[base2], vc1 = x4[base2 + 64];

    // ================= Layer 1 =================
    {
        CT g[4] = { ct2(vb0.x, vb0.z), ct2(vb0.y, vb0.w),
                    ct2(vb1.x, vb1.z), ct2(vb1.y, vb1.w) };
#pragma unroll
        for (int w = 0; w < 4; w++) {
            Cacc = mul2(Cacc, g[w].c);
            u64 t = g[w].t, nt = neg2(t);
            int m = 8 >> w;
#pragma unroll
            for (int k = 0; k < 32; k++) {
                if (!(k & m)) {
                    int k1 = k | m;
                    u64 a0r = sr[k],  a0i = si[k];
                    u64 a1r = sr[k1], a1i = si[k1];
                    sr[k]  = fma2(t,  a1i, a0r);
                    si[k]  = fma2(nt, a1r, a0i);
                    sr[k1] = fma2(t,  a0i, a1r);
                    si[k1] = fma2(nt, a0r, a1i);
                }
            }
        }
        {
            Cp c[16];
            coef_table(thetas, 1, c);
            mono_apply(sr, si, 0,  c);
            mono_apply(sr, si, 16, c);
        }
        // CPhase-1 on upper half, n&8
        {
            float ps_, pc_;
            __sincosf(phis[1], &ps_, &pc_);
            u64 pr = pk2b(pc_), pi = pk2b(ps_);
            u64 npi = neg2(pi);
#pragma unroll
            for (int n = 8; n < 16; n++) {
                u64 ar = sr[16 + n], ai = si[16 + n];
                sr[16 + n] = fma2(npi, ai, mul2(pr, ar));
                si[16 + n] = fma2(pi,  ar, mul2(pr, ai));
            }
        }
    }

    // ================= Layer 2 (CPhase-2 folded into reduce) =================
    {
        CT g[4] = { ct2(vc0.x, vc0.z), ct2(vc0.y, vc0.w),
                    ct2(vc1.x, vc1.z), ct2(vc1.y, vc1.w) };
#pragma unroll
        for (int w = 0; w < 4; w++) {
            Cacc = mul2(Cacc, g[w].c);
            u64 t = g[w].t, nt = neg2(t);
            int m = 8 >> w;
#pragma unroll
            for (int k = 0; k < 32; k++) {
                if (!(k & m)) {
                    int k1 = k | m;
                    u64 a0r = sr[k],  a0i = si[k];
                    u64 a1r = sr[k1], a1i = si[k1];
                    sr[k]  = fma2(t,  a1i, a0r);
                    si[k]  = fma2(nt, a1r, a0i);
                    sr[k1] = fma2(t,  a0i, a1r);
                    si[k1] = fma2(nt, a0r, a1i);
                }
            }
        }
        {
            Cp c[16];
            coef_table(thetas, 2, c);
            mono_apply(sr, si, 0,  c);
            mono_apply(sr, si, 16, c);
        }
    }

    // Final: ev = 2*C^2 * Re[ S0 + e^{i phi2} S1 ],
    //  S0 = sum_{n&8==0} conj(a_n) b_n,  S1 = sum_{n&8} conj(a_n) b_n
    u64 accR0 = 0ULL, accR1 = 0ULL, accI1 = 0ULL;
#pragma unroll
    for (int n = 0; n < 16; n++) {
        u64 ar = sr[n], ai = si[n];
        u64 br = sr[n + 16], bi = si[n + 16];
        if (n & 8) {
            accR1 = fma2(ar, br, accR1);
            accR1 = fma2(ai, bi, accR1);
            accI1 = fma2(ar, bi, accI1);
            accI1 = fma2(neg2(ai), br, accI1);
        } else {
            accR0 = fma2(ar, br, accR0);
            accR0 = fma2(ai, bi, accR0);
        }
    }
    {
        float ps_, pc_;
        __sincosf(phis[2], &ps_, &pc_);
        u64 cph = pk2b(pc_), sph = pk2b(ps_);
        u64 re = fma2(cph, accR1, accR0);
        re = fma2(neg2(sph), accI1, re);
        u64 C2 = mul2(Cacc, Cacc);
        re = mul2(re, mul2(C2, pk2b(2.0f)));

        float lo, hi;
        upk2(lo, hi, re);
        ((float2*)out)[q] = make_float2(lo, hi);
    }
}

extern "C" void kernel_launch(void* const* d_in, const int* in_sizes, int n_in,
                              void* d_out, int out_size) {
    const float* x      = (const float*)d_in[0];
    const float* thetas = (const float*)d_in[1];
    const float* phis   = (const float*)d_in[2];
    float* out = (float*)d_out;

    sim_kernel<<<PPAIRS / 128, 128>>>(x, thetas, phis, out);
}

// round 12
// speedup vs baseline: 1.1555x; 1.1361x over previous
#include <cuda_runtime.h>

typedef unsigned long long u64;

// x [16,3,256,256] f32, thetas[12], phis[3] -> out [16,1,128,128] f32
#define PPAIRS (16 * 128 * 64)   // 131072 threads, 2 patches each

// ---- packed f32x2 helpers (lanes = 2 adjacent patches) ----
__device__ __forceinline__ u64 pk2(float lo, float hi) {
    u64 r; asm("mov.b64 %0,{%1,%2};" : "=l"(r) : "f"(lo), "f"(hi)); return r;
}
__device__ __forceinline__ u64 pk2b(float v) { return pk2(v, v); }
__device__ __forceinline__ void upk2(float& lo, float& hi, u64 v) {
    asm("mov.b64 {%0,%1},%2;" : "=f"(lo), "=f"(hi) : "l"(v));
}
__device__ __forceinline__ u64 fma2(u64 a, u64 b, u64 c) {
    u64 d; asm("fma.rn.f32x2 %0,%1,%2,%3;" : "=l"(d) : "l"(a), "l"(b), "l"(c)); return d;
}
__device__ __forceinline__ u64 mul2(u64 a, u64 b) {
    u64 d; asm("mul.rn.f32x2 %0,%1,%2;" : "=l"(d) : "l"(a), "l"(b)); return d;
}
__device__ __forceinline__ u64 neg2(u64 a) {
    const u64 SGN = 0x8000000080000000ULL;
    u64 d; asm("xor.b64 %0,%1,%2;" : "=l"(d) : "l"(a), "l"(SGN)); return d;
}

struct CS { u64 c, s; };
__device__ __forceinline__ CS cs2(float alo, float ahi) {
    float sl, cl, sh, ch;
    __sincosf(0.5f * alo, &sl, &cl);
    __sincosf(0.5f * ahi, &sh, &ch);
    CS r; r.c = pk2(cl, ch); r.s = pk2(sl, sh); return r;
}
struct CT { u64 c, t; };  // cos (uniform scale) + tan (butterfly)
__device__ __forceinline__ CT ct2(float alo, float ahi) {
    float sl, cl, sh, ch;
    __sincosf(0.5f * alo, &sl, &cl);
    __sincosf(0.5f * ahi, &sh, &ch);
    CT r; r.c = pk2(cl, ch);
    r.t = pk2(__fdividef(sl, cl), __fdividef(sh, ch));
    return r;
}

// packed complex
struct Cp { u64 r, i; };
__device__ __forceinline__ Cp cmul(Cp a, Cp b) {
    Cp d;
    d.r = fma2(neg2(a.i), b.i, mul2(a.r, b.r));
    d.i = fma2(a.i, b.r, mul2(a.r, b.i));
    return d;
}

// CU-ring monomial: new[PERM[k]] = coef[k] * old[k] (per 4-wire half-space).
// f1 = sin - i cos (ctrl&tgt both 1), f2 = -conj(f1). k=0 fixed point, coef 1.
__device__ __forceinline__ void coef_table(const float* __restrict__ thetas,
                                           int L, Cp* c) {
    Cp f1[4], f2[4];
#pragma unroll
    for (int w = 0; w < 4; w++) {
        float s_, c_;
        __sincosf(0.5f * thetas[4 * L + w], &s_, &c_);
        f1[w].r = pk2b(s_);  f1[w].i = pk2b(-c_);
        f2[w].r = neg2(f1[w].r);  f2[w].i = f1[w].i;   // f2 = -conj(f1)
    }
    c[1]  = f2[3];
    c[3]  = f1[2];
    c[6]  = f1[1];
    c[12] = f1[0];
    c[2]  = cmul(f2[2], f2[3]);
    c[4]  = cmul(f2[1], c[2]);
    c[5]  = cmul(f2[1], f1[2]);
    c[7]  = cmul(f1[1], f2[3]);
    Cp E  = cmul(f2[0], f2[1]);
    c[9]  = cmul(E, f1[2]);
    Cp T  = cmul(f2[2], f1[3]);
    c[8]  = cmul(E, T);
    c[10] = cmul(f2[0], f1[1]);
    c[11] = cmul(c[10], f1[3]);
    c[13] = cmul(f1[0], f1[3]);
    c[14] = cmul(c[13], f2[2]);
    c[15] = cmul(f1[0], f1[2]);
}

__device__ __constant__ const int PERM[16] = {0,9,11,2,15,6,4,13,7,14,12,5,8,1,3,10};

// Apply monomial in place over 16 amps at offset O.
__device__ __forceinline__ void mono_apply(u64* sr, u64* si, int O, const Cp* c) {
    u64 tr[16], ti[16];
    tr[0] = sr[O]; ti[0] = si[O];
#pragma unroll
    for (int k = 1; k < 16; k++) {
        int m = PERM[k];
        u64 ar = sr[O + k], ai = si[O + k];
        u64 nci = neg2(c[k].i);
        tr[m] = fma2(nci,    ai, mul2(c[k].r, ar));
        ti[m] = fma2(c[k].i, ar, mul2(c[k].r, ai));
    }
#pragma unroll
    for (int k = 0; k < 16; k++) { sr[O + k] = tr[k]; si[O + k] = ti[k]; }
}

// tan-trick RX butterfly over NAMPS amps, target mask m
template <int NAMPS>
__device__ __forceinline__ void rx_gate(u64* sr, u64* si, int m, u64 t) {
    u64 nt = neg2(t);
#pragma unroll
    for (int k = 0; k < NAMPS; k++) {
        if (!(k & m)) {
            int k1 = k | m;
            u64 a0r = sr[k],  a0i = si[k];
            u64 a1r = sr[k1], a1i = si[k1];
            sr[k]  = fma2(t,  a1i, a0r);
            si[k]  = fma2(nt, a1r, a0i);
            sr[k1] = fma2(t,  a0i, a1r);
            si[k1] = fma2(nt, a0r, a1i);
        }
    }
}

// Full 32-amp state: k = w0*16 + n,  n = w1*8 + w2*4 + w3*2 + w4
__global__ void __launch_bounds__(128, 3)
sim_kernel(const float* __restrict__ x,
           const float* __restrict__ thetas,
           const float* __restrict__ phis,
           float* __restrict__ out) {
    int q   = blockIdx.x * 128 + threadIdx.x;
    int b   = q >> 13;
    int rem = q & 8191;
    int i   = rem >> 6;
    int jp  = rem & 63;

    const float4* __restrict__ x4 = (const float4*)x;
    int base0 = ((b * 3 + 0) * 256 + 2 * i) * 64 + jp;
    int base1 = base0 + 256 * 64;
    int base2 = base1 + 256 * 64;

    // software-pipelined loads: L0 + L1 in flight immediately
    float4 va0 = x4[base0], va1 = x4[base0 + 64];
    float4 vb0 = x4[base1], vb1 = x4[base1 + 64];

    u64 sr[32], si[32];

    // ================= Layer 0: product state (16 amps) =================
    {
        CS g0 = cs2(va0.x, va0.z), g1 = cs2(va0.y, va0.w);
        CS g2 = cs2(va1.x, va1.z), g3 = cs2(va1.y, va1.w);

        u64 INV2 = pk2b(0.70710678118654752f);
        u64 c0 = mul2(g0.c, INV2), s0 = mul2(g0.s, INV2);
        u64 ab[4] = { mul2(c0, g1.c), mul2(c0, g1.s), mul2(s0, g1.c), mul2(s0, g1.s) };
        u64 cd[4] = { mul2(g2.c, g3.c), mul2(g2.c, g3.s), mul2(g2.s, g3.c), mul2(g2.s, g3.s) };
#pragma unroll
        for (int n = 0; n < 16; n++) {
            u64 m = mul2(ab[n >> 2], cd[n & 3]);
            int pc = __popc(n) & 3;
            if (pc == 0)      { sr[n] = m;        si[n] = 0ULL;     }
            else if (pc == 1) { sr[n] = 0ULL;     si[n] = neg2(m);  }
            else if (pc == 2) { sr[n] = neg2(m);  si[n] = 0ULL;     }
            else              { sr[n] = 0ULL;     si[n] = m;        }
        }
    }

    // ---- Layer-0 CU ring as monomial on the 16-amp state ----
    {
        Cp c[16];
        coef_table(thetas, 0, c);
        mono_apply(sr, si, 0, c);
    }

    u64 Cacc;  // packed uniform RX cos scale (layers 1,2)

    // prefetch layer-2 pixels before layer-1 compute
    float4 vc0 = x4[base2], vc1 = x4[base2 + 64];

    // ================= Layer 1 =================
    {
        CT g[4] = { ct2(vb0.x, vb0.z), ct2(vb0.y, vb0.w),
                    ct2(vb1.x, vb1.z), ct2(vb1.y, vb1.w) };
        Cacc = mul2(mul2(g[0].c, g[1].c), mul2(g[2].c, g[3].c));

        // RX w2,w3,w4 on the 16-amp lower state (commute with CPhase-0 on w1)
        rx_gate<16>(sr, si, 4, g[1].t);
        rx_gate<16>(sr, si, 2, g[2].t);
        rx_gate<16>(sr, si, 1, g[3].t);

        // Split into wire0 branches (CPhase-0 phase on n&8)
        {
            float ps_, pc_;
            __sincosf(phis[0], &ps_, &pc_);
            u64 pr = pk2b(pc_), pi = pk2b(ps_);
            u64 npi = neg2(pi);
#pragma unroll
            for (int n = 0; n < 16; n++) {
                if (n & 8) {
                    sr[16 + n] = fma2(npi, si[n], mul2(pr, sr[n]));
                    si[16 + n] = fma2(pi,  sr[n], mul2(pr, si[n]));
                } else {
                    sr[16 + n] = sr[n];
                    si[16 + n] = si[n];
                }
            }
        }

        // RX w1 on the full 32-amp state
        rx_gate<32>(sr, si, 8, g[0].t);

        // CU ring monomial on both halves
        {
            Cp c[16];
            coef_table(thetas, 1, c);
            mono_apply(sr, si, 0,  c);
            mono_apply(sr, si, 16, c);
        }
        // CPhase-1 on upper half, n&8
        {
            float ps_, pc_;
            __sincosf(phis[1], &ps_, &pc_);
            u64 pr = pk2b(pc_), pi = pk2b(ps_);
            u64 npi = neg2(pi);
#pragma unroll
            for (int n = 8; n < 16; n++) {
                u64 ar = sr[16 + n], ai = si[16 + n];
                sr[16 + n] = fma2(npi, ai, mul2(pr, ar));
                si[16 + n] = fma2(pi,  ar, mul2(pr, ai));
            }
        }
    }

    // ================= Layer 2: RX only =================
    // The layer-2 CU ring is a monomial with unit-modulus coefs: it cancels in
    // the inner product, leaving only CPhase-2's phase pattern on the
    // permuted index set K1 = {k : PERM[k]&8}.
    {
        CT g[4] = { ct2(vc0.x, vc0.z), ct2(vc0.y, vc0.w),
                    ct2(vc1.x, vc1.z), ct2(vc1.y, vc1.w) };
        Cacc = mul2(Cacc, mul2(mul2(g[0].c, g[1].c), mul2(g[2].c, g[3].c)));
        rx_gate<32>(sr, si, 8, g[0].t);
        rx_gate<32>(sr, si, 4, g[1].t);
        rx_gate<32>(sr, si, 2, g[2].t);
        rx_gate<32>(sr, si, 1, g[3].t);
    }

    // Final: ev = 2*C^2 * Re[ S0 + e^{i phi2} S1 ],
    //  S1 over k in K1 = {1,2,4,7,9,10,12,15}, S0 over the rest.
    u64 accR0 = 0ULL, accR1 = 0ULL, accI1 = 0ULL;
#pragma unroll
    for (int n = 0; n < 16; n++) {
        const bool inK1 = (n==1)||(n==2)||(n==4)||(n==7)||(n==9)||(n==10)||(n==12)||(n==15);
        u64 ar = sr[n], ai = si[n];
        u64 br = sr[n + 16], bi = si[n + 16];
        if (inK1) {
            accR1 = fma2(ar, br, accR1);
            accR1 = fma2(ai, bi, accR1);
            accI1 = fma2(ar, bi, accI1);
            accI1 = fma2(neg2(ai), br, accI1);
        } else {
            accR0 = fma2(ar, br, accR0);
            accR0 = fma2(ai, bi, accR0);
        }
    }
    {
        float ps_, pc_;
        __sincosf(phis[2], &ps_, &pc_);
        u64 cph = pk2b(pc_), sph = pk2b(ps_);
        u64 re = fma2(cph, accR1, accR0);
        re = fma2(neg2(sph), accI1, re);
        u64 C2 = mul2(Cacc, Cacc);
        re = mul2(re, mul2(C2, pk2b(2.0f)));

        float lo, hi;
        upk2(lo, hi, re);
        ((float2*)out)[q] = make_float2(lo, hi);
    }
}

extern "C" void kernel_launch(void* const* d_in, const int* in_sizes, int n_in,
                              void* d_out, int out_size) {
    const float* x      = (const float*)d_in[0];
    const float* thetas = (const float*)d_in[1];
    const float* phis   = (const float*)d_in[2];
    float* out = (float*)d_out;

    sim_kernel<<<PPAIRS / 128, 128>>>(x, thetas, phis, out);
}

// round 13
// speedup vs baseline: 1.1580x; 1.0022x over previous
#include <cuda_runtime.h>

typedef unsigned long long u64;

// x [16,3,256,256] f32, thetas[12], phis[3] -> out [16,1,128,128] f32
#define PPAIRS (16 * 128 * 64)   // 131072 threads, 2 patches each

// ---- packed f32x2 helpers (lanes = 2 adjacent patches) ----
__device__ __forceinline__ u64 pk2(float lo, float hi) {
    u64 r; asm("mov.b64 %0,{%1,%2};" : "=l"(r) : "f"(lo), "f"(hi)); return r;
}
__device__ __forceinline__ u64 pk2b(float v) { return pk2(v, v); }
__device__ __forceinline__ void upk2(float& lo, float& hi, u64 v) {
    asm("mov.b64 {%0,%1},%2;" : "=f"(lo), "=f"(hi) : "l"(v));
}
__device__ __forceinline__ u64 fma2(u64 a, u64 b, u64 c) {
    u64 d; asm("fma.rn.f32x2 %0,%1,%2,%3;" : "=l"(d) : "l"(a), "l"(b), "l"(c)); return d;
}
__device__ __forceinline__ u64 mul2(u64 a, u64 b) {
    u64 d; asm("mul.rn.f32x2 %0,%1,%2;" : "=l"(d) : "l"(a), "l"(b)); return d;
}
__device__ __forceinline__ u64 neg2(u64 a) {
    const u64 SGN = 0x8000000080000000ULL;
    u64 d; asm("xor.b64 %0,%1,%2;" : "=l"(d) : "l"(a), "l"(SGN)); return d;
}

struct CS { u64 c, s; };
__device__ __forceinline__ CS cs2(float alo, float ahi) {
    float sl, cl, sh, ch;
    __sincosf(0.5f * alo, &sl, &cl);
    __sincosf(0.5f * ahi, &sh, &ch);
    CS r; r.c = pk2(cl, ch); r.s = pk2(sl, sh); return r;
}
struct CT { u64 c, t; };  // cos (uniform scale) + tan (butterfly)
__device__ __forceinline__ CT ct2(float alo, float ahi) {
    float sl, cl, sh, ch;
    __sincosf(0.5f * alo, &sl, &cl);
    __sincosf(0.5f * ahi, &sh, &ch);
    CT r; r.c = pk2(cl, ch);
    r.t = pk2(__fdividef(sl, cl), __fdividef(sh, ch));
    return r;
}

// packed complex
struct Cp { u64 r, i; };
__device__ __forceinline__ Cp cmul(Cp a, Cp b) {
    Cp d;
    d.r = fma2(neg2(a.i), b.i, mul2(a.r, b.r));
    d.i = fma2(a.i, b.r, mul2(a.r, b.i));
    return d;
}

// CU-ring monomial: new[PERM[k]] = coef[k] * old[k] (per 4-wire half-space).
// f1 = sin - i cos (ctrl&tgt both 1), f2 = -conj(f1). k=0 fixed point, coef 1.
__device__ __forceinline__ void coef_table(const float* __restrict__ thetas,
                                           int L, Cp* c) {
    Cp f1[4], f2[4];
#pragma unroll
    for (int w = 0; w < 4; w++) {
        float s_, c_;
        __sincosf(0.5f * thetas[4 * L + w], &s_, &c_);
        f1[w].r = pk2b(s_);  f1[w].i = pk2b(-c_);
        f2[w].r = neg2(f1[w].r);  f2[w].i = f1[w].i;   // f2 = -conj(f1)
    }
    c[1]  = f2[3];
    c[3]  = f1[2];
    c[6]  = f1[1];
    c[12] = f1[0];
    c[2]  = cmul(f2[2], f2[3]);
    c[4]  = cmul(f2[1], c[2]);
    c[5]  = cmul(f2[1], f1[2]);
    c[7]  = cmul(f1[1], f2[3]);
    Cp E  = cmul(f2[0], f2[1]);
    c[9]  = cmul(E, f1[2]);
    Cp T  = cmul(f2[2], f1[3]);
    c[8]  = cmul(E, T);
    c[10] = cmul(f2[0], f1[1]);
    c[11] = cmul(c[10], f1[3]);
    c[13] = cmul(f1[0], f1[3]);
    c[14] = cmul(c[13], f2[2]);
    c[15] = cmul(f1[0], f1[2]);
}

__device__ __constant__ const int PERM[16] = {0,9,11,2,15,6,4,13,7,14,12,5,8,1,3,10};
// 15-cycle of PERM in application order (PERM[CYC[i]] == CYC[i+1]):
__device__ __constant__ const int CYC[15] = {1,9,14,3,2,11,5,6,4,15,10,12,8,7,13};

// In-place monomial over 16 amps at offset O with in-register coefs.
__device__ __forceinline__ void mono_inplace(u64* sr, u64* si, int O, const Cp* c) {
    u64 tR = sr[O + 13], tI = si[O + 13];
#pragma unroll
    for (int ii = 13; ii >= 0; ii--) {
        const int s_ = CYC[ii], d_ = CYC[ii + 1];
        u64 ar = sr[O + s_], ai = si[O + s_];
        u64 nci = neg2(c[s_].i);
        sr[O + d_] = fma2(nci,     ai, mul2(c[s_].r, ar));
        si[O + d_] = fma2(c[s_].i, ar, mul2(c[s_].r, ai));
    }
    {   // close the cycle: new[CYC[0]=1] = c[13] * old[13]
        u64 nci = neg2(c[13].i);
        sr[O + 1] = fma2(nci,      tI, mul2(c[13].r, tR));
        si[O + 1] = fma2(c[13].i,  tR, mul2(c[13].r, tI));
    }
}

// tan-trick RX butterfly over NAMPS amps, target mask m
template <int NAMPS>
__device__ __forceinline__ void rx_gate(u64* sr, u64* si, int m, u64 t) {
    u64 nt = neg2(t);
#pragma unroll
    for (int k = 0; k < NAMPS; k++) {
        if (!(k & m)) {
            int k1 = k | m;
            u64 a0r = sr[k],  a0i = si[k];
            u64 a1r = sr[k1], a1i = si[k1];
            sr[k]  = fma2(t,  a1i, a0r);
            si[k]  = fma2(nt, a1r, a0i);
            sr[k1] = fma2(t,  a0i, a1r);
            si[k1] = fma2(nt, a0r, a1i);
        }
    }
}

// Full 32-amp state: k = w0*16 + n,  n = w1*8 + w2*4 + w3*2 + w4
__global__ void __launch_bounds__(128, 3)
sim_kernel(const float* __restrict__ x,
           const float* __restrict__ thetas,
           const float* __restrict__ phis,
           float* __restrict__ out) {
    int q   = blockIdx.x * 128 + threadIdx.x;
    int b   = q >> 13;
    int rem = q & 8191;
    int i   = rem >> 6;
    int jp  = rem & 63;

    const float4* __restrict__ x4 = (const float4*)x;
    int base0 = ((b * 3 + 0) * 256 + 2 * i) * 64 + jp;
    int base1 = base0 + 256 * 64;
    int base2 = base1 + 256 * 64;

    // software-pipelined loads: L0 + L1 in flight immediately
    float4 va0 = x4[base0], va1 = x4[base0 + 64];
    float4 vb0 = x4[base1], vb1 = x4[base1 + 64];

    u64 sr[32], si[32];

    // ===== Layer 0: product state with CU-ring monomial folded in ==========
    // s[PERM[k]] = (c_k * (-i)^popc(k)) * m(k),  m real, includes 1/sqrt2.
    {
        CS g0 = cs2(va0.x, va0.z), g1 = cs2(va0.y, va0.w);
        CS g2 = cs2(va1.x, va1.z), g3 = cs2(va1.y, va1.w);

        u64 INV2 = pk2b(0.70710678118654752f);
        u64 c0 = mul2(g0.c, INV2), s0 = mul2(g0.s, INV2);
        u64 ab[4] = { mul2(c0, g1.c), mul2(c0, g1.s), mul2(s0, g1.c), mul2(s0, g1.s) };
        u64 cd[4] = { mul2(g2.c, g3.c), mul2(g2.c, g3.s), mul2(g2.s, g3.c), mul2(g2.s, g3.s) };

        Cp c[16];
        coef_table(thetas, 0, c);
        c[0].r = pk2b(1.0f);  c[0].i = 0ULL;

#pragma unroll
        for (int k = 0; k < 16; k++) {
            u64 m = mul2(ab[k >> 2], cd[k & 3]);
            int p = __popc(k) & 3;               // compile-time constant
            u64 dr, di;
            if (p == 0)      { dr = c[k].r;        di = c[k].i;        }
            else if (p == 1) { dr = c[k].i;        di = neg2(c[k].r);  }
            else if (p == 2) { dr = neg2(c[k].r);  di = neg2(c[k].i);  }
            else             { dr = neg2(c[k].i);  di = c[k].r;        }
            sr[PERM[k]] = mul2(dr, m);
            si[PERM[k]] = mul2(di, m);
        }
    }

    u64 Cacc;  // packed uniform RX cos scale (layers 1,2)

    // prefetch layer-2 pixels before layer-1 compute
    float4 vc0 = x4[base2], vc1 = x4[base2 + 64];

    // ================= Layer 1 =================
    {
        CT g[4] = { ct2(vb0.x, vb0.z), ct2(vb0.y, vb0.w),
                    ct2(vb1.x, vb1.z), ct2(vb1.y, vb1.w) };
        Cacc = mul2(mul2(g[0].c, g[1].c), mul2(g[2].c, g[3].c));

        // RX w2,w3,w4 on the 16-amp lower state (commute with CPhase-0 on w1)
        rx_gate<16>(sr, si, 4, g[1].t);
        rx_gate<16>(sr, si, 2, g[2].t);
        rx_gate<16>(sr, si, 1, g[3].t);

        // Split into wire0 branches (CPhase-0 phase on n&8)
        {
            float ps_, pc_;
            __sincosf(phis[0], &ps_, &pc_);
            u64 pr = pk2b(pc_), pi = pk2b(ps_);
            u64 npi = neg2(pi);
#pragma unroll
            for (int n = 0; n < 16; n++) {
                if (n & 8) {
                    sr[16 + n] = fma2(npi, si[n], mul2(pr, sr[n]));
                    si[16 + n] = fma2(pi,  sr[n], mul2(pr, si[n]));
                } else {
                    sr[16 + n] = sr[n];
                    si[16 + n] = si[n];
                }
            }
        }

        // RX w1 on the full 32-amp state
        rx_gate<32>(sr, si, 8, g[0].t);

        // CU ring monomial on both halves (in place, in-register coefs)
        {
            Cp c[16];
            coef_table(thetas, 1, c);
            mono_inplace(sr, si, 0,  c);
            mono_inplace(sr, si, 16, c);
        }
        // CPhase-1 on upper half, n&8
        {
            float ps_, pc_;
            __sincosf(phis[1], &ps_, &pc_);
            u64 pr = pk2b(pc_), pi = pk2b(ps_);
            u64 npi = neg2(pi);
#pragma unroll
            for (int n = 8; n < 16; n++) {
                u64 ar = sr[16 + n], ai = si[16 + n];
                sr[16 + n] = fma2(npi, ai, mul2(pr, ar));
                si[16 + n] = fma2(pi,  ar, mul2(pr, ai));
            }
        }
    }

    // ================= Layer 2: RX only =================
    // Layer-2 CU ring is a unit-modulus monomial: cancels in the inner
    // product; CPhase-2 survives on K1 = {k : PERM[k]&8} = odd parity of
    // wires 2,3,4.
    {
        CT g[4] = { ct2(vc0.x, vc0.z), ct2(vc0.y, vc0.w),
                    ct2(vc1.x, vc1.z), ct2(vc1.y, vc1.w) };
        Cacc = mul2(Cacc, mul2(mul2(g[0].c, g[1].c), mul2(g[2].c, g[3].c)));
        rx_gate<32>(sr, si, 8, g[0].t);
        rx_gate<32>(sr, si, 4, g[1].t);
        rx_gate<32>(sr, si, 2, g[2].t);
        rx_gate<32>(sr, si, 1, g[3].t);
    }

    // Final: ev = 2*C^2 * Re[ S0 + e^{i phi2} S1 ],  S1 over K1 (odd popc of n&7)
    u64 accR0 = 0ULL, accR1 = 0ULL, accI1 = 0ULL;
#pragma unroll
    for (int n = 0; n < 16; n++) {
        const bool inK1 = (__popc(n & 7) & 1) != 0;
        u64 ar = sr[n], ai = si[n];
        u64 br = sr[n + 16], bi = si[n + 16];
        if (inK1) {
            accR1 = fma2(ar, br, accR1);
            accR1 = fma2(ai, bi, accR1);
            accI1 = fma2(ar, bi, accI1);
            accI1 = fma2(neg2(ai), br, accI1);
        } else {
            accR0 = fma2(ar, br, accR0);
            accR0 = fma2(ai, bi, accR0);
        }
    }
    {
        float ps_, pc_;
        __sincosf(phis[2], &ps_, &pc_);
        u64 cph = pk2b(pc_), sph = pk2b(ps_);
        u64 re = fma2(cph, accR1, accR0);
        re = fma2(neg2(sph), accI1, re);
        u64 C2 = mul2(Cacc, Cacc);
        re = mul2(re, mul2(C2, pk2b(2.0f)));

        float lo, hi;
        upk2(lo, hi, re);
        ((float2*)out)[q] = make_float2(lo, hi);
    }
}

extern "C" void kernel_launch(void* const* d_in, const int* in_sizes, int n_in,
                              void* d_out, int out_size) {
    const float* x      = (const float*)d_in[0];
    const float* thetas = (const float*)d_in[1];
    const float* phis   = (const float*)d_in[2];
    float* out = (float*)d_out;

    sim_kernel<<<PPAIRS / 128, 128>>>(x, thetas, phis, out);
}